// round 8
// baseline (speedup 1.0000x reference)
#include <cuda_runtime.h>
#include <cstdint>

typedef unsigned long long u64;
typedef unsigned int u32;

#define NPRED   25200
#define NCH     85
#define NBATCH  16
#define TOPK    2048
#define MAXDET  300
#define CONF    0.25f
#define NMS_T   0.45f
#define WSZ     256         // NMS window size
#define WW      8           // u32 words per window row (WSZ/32)
#define NBIN    8192
#define HBLK    4           // histogram sub-blocks per batch
#define HCHUNK  (NPRED / HBLK)   // 6300
#define CANDCAP 8192
#define KBASE   0xBE800000u // sortable(+0.25); valid keys in (KBASE, KBASE+2^24)

__device__ u32    g_hist[NBATCH * HBLK * NBIN];
__device__ u64    g_cand[NBATCH * CANDCAP];
__device__ int    g_M[NBATCH];
__device__ float4 g_box  [NBATCH * TOPK];
__device__ float  g_area [NBATCH * TOPK];
__device__ float  g_score[NBATCH * TOPK];
__device__ int    g_orig [NBATCH * TOPK];
__device__ int    g_nvalid[NBATCH];

__device__ __forceinline__ unsigned f2sortable(float f) {
    unsigned v = __float_as_uint(f);
    return (v & 0x80000000u) ? ~v : (v | 0x80000000u);
}
__device__ __forceinline__ float sortable2f(unsigned s) {
    unsigned v = (s & 0x80000000u) ? (s & 0x7FFFFFFFu) : ~s;
    return __uint_as_float(v);
}

// Bitwise-identical to (inter/(union+1e-7)) > 0.45: multiply-compare bracket,
// exact division only inside the ±4e-6 ambiguity band (div err ~6e-8).
__device__ __forceinline__ bool sup_test(float4 a, float aa, float4 bb, float ab) {
    float ltx = fmaxf(a.x, bb.x);
    float lty = fmaxf(a.y, bb.y);
    float rbx = fminf(a.z, bb.z);
    float rby = fminf(a.w, bb.w);
    float iw  = fmaxf(__fsub_rn(rbx, ltx), 0.0f);
    float ih  = fmaxf(__fsub_rn(rby, lty), 0.0f);
    float inter = __fmul_rn(iw, ih);
    float uni   = __fsub_rn(__fadd_rn(ab, aa), inter);
    float u     = __fadd_rn(uni, 1e-7f);
    if (inter > __fmul_rn(u, 0.45000180f)) return true;
    if (inter < __fmul_rn(u, 0.44999820f)) return false;
    return __fdiv_rn(inter, u) > NMS_T;
}

// ---------------------------------------------------------------------------
// K1: per (batch, sub-block) histogram of score keys. Plain stores into the
//     block's own slice — no zero kernel, no global atomics.
// ---------------------------------------------------------------------------
__global__ __launch_bounds__(512, 2)
void k_hist(const float* __restrict__ preds) {
    __shared__ u32 h[NBIN];
    const int b = blockIdx.x, p = blockIdx.y, tid = threadIdx.x;
    for (int i = tid; i < NBIN; i += 512) h[i] = 0;
    __syncthreads();
    const int start = p * HCHUNK;
    for (int i = start + tid; i < start + HCHUNK; i += 512) {
        float sv = preds[((size_t)b * NPRED + i) * NCH + 4];
        if (sv > CONF) {
            u32 s = f2sortable(sv);
            u32 bin = (s - KBASE) >> 11;
            if (bin > NBIN - 1) bin = NBIN - 1;
            atomicAdd(&h[bin], 1u);
        }
    }
    __syncthreads();
    u32* dst = g_hist + ((size_t)(b * HBLK + p) << 13);
    for (int i = tid; i < NBIN; i += 512) dst[i] = h[i];
}

// ---------------------------------------------------------------------------
// K2: per batch — suffix-scan bins to boundary bin B (smallest start with
//     suffix count >= 2048), then compact keys >= threshold into g_cand.
// ---------------------------------------------------------------------------
__global__ __launch_bounds__(1024, 1)
void k_compact(const float* __restrict__ preds) {
    __shared__ u32 binCnt[NBIN];
    __shared__ u32 part[1024];
    __shared__ int sB;
    __shared__ int cnt;
    const int b = blockIdx.x, tid = threadIdx.x;

    const u32* hb = g_hist + ((size_t)(b * HBLK) << 13);
    u32 sum = 0;
    #pragma unroll
    for (int k = 0; k < 8; ++k) {
        int bin = tid * 8 + k;
        u32 c = hb[bin] + hb[NBIN + bin] + hb[2 * NBIN + bin] + hb[3 * NBIN + bin];
        binCnt[bin] = c;
        sum += c;
    }
    part[tid] = sum;
    __syncthreads();
    // inclusive suffix scan over 1024 group sums (Hillis-Steele)
    for (int d = 1; d < 1024; d <<= 1) {
        u32 v = (tid + d < 1024) ? part[tid + d] : 0u;
        __syncthreads();
        part[tid] += v;
        __syncthreads();
    }
    if (tid == 0) sB = 0;                 // default: take everything valid
    __syncthreads();
    {
        u32 below = (tid + 1 < 1024) ? part[tid + 1] : 0u;
        if (part[tid] >= TOPK && below < TOPK) {   // unique boundary group
            u32 acc = below;
            int B = tid * 8;
            for (int k = 7; k >= 0; --k) {
                acc += binCnt[tid * 8 + k];
                if (acc >= TOPK) { B = tid * 8 + k; break; }
            }
            sB = B;
        }
    }
    if (tid == 0) cnt = 0;
    __syncthreads();
    const u32 thr = KBASE + ((u32)sB << 11);

    for (int i = tid; i < NPRED; i += 1024) {
        float sv = preds[((size_t)b * NPRED + i) * NCH + 4];
        if (sv > CONF) {
            u32 s = f2sortable(sv);
            if (s >= thr) {
                int pos = atomicAdd(&cnt, 1);
                if (pos < CANDCAP)
                    g_cand[b * CANDCAP + pos] =
                        ((u64)s << 32) | (u32)(~(u32)i);
            }
        }
    }
    __syncthreads();
    if (tid == 0) g_M[b] = (cnt < CANDCAP) ? cnt : CANDCAP;
}

// ---------------------------------------------------------------------------
// K3: per batch — ONE bitonic sort (n = next pow2 >= M, >= 2048) descending,
//     then decode/clip top-2048 boxes into SoA scratch.
// ---------------------------------------------------------------------------
__global__ __launch_bounds__(1024, 1)
void k_sortdec(const float* __restrict__ preds,
               const int* __restrict__ image_sizes) {
    extern __shared__ u64 s[];          // up to 8192 keys = 64KB
    const int b = blockIdx.x, tid = threadIdx.x;
    int M = g_M[b];
    int n = 2048;
    while (n < M) n <<= 1;              // <= 8192 by CANDCAP

    for (int r = tid; r < n; r += 1024)
        s[r] = (r < M) ? g_cand[b * CANDCAP + r] : 0ULL;

    for (u32 k = 2; k <= (u32)n; k <<= 1) {
        for (u32 j = k >> 1; j > 0; j >>= 1) {
            __syncthreads();
            for (u32 t = tid; t < (u32)n / 2; t += 1024) {
                u32 i = 2u * t - (t & (j - 1));
                u32 l = i + j;
                u64 a = s[i], e = s[l];
                bool dir = ((i & k) == 0);
                if ((a < e) == dir) { s[i] = e; s[l] = a; }
            }
        }
    }
    __syncthreads();

    const float H  = (float)image_sizes[b * 2 + 0];
    const float W  = (float)image_sizes[b * 2 + 1];
    const float rh = __fdiv_rn(H, 640.0f);
    const float rw = __fdiv_rn(W, 640.0f);

    for (int r = tid; r < TOPK; r += 1024) {
        u64 key = (r < n) ? s[r] : 0ULL;
        unsigned o = ~((unsigned)key);
        int gi = b * TOPK + r;
        if (key != 0ULL && o < NPRED) {
            float sc = sortable2f((unsigned)(key >> 32));
            const float* p = preds + ((size_t)b * NPRED + o) * NCH;
            float x = p[0], y = p[1], w = p[2], h = p[3];
            float xm = __fsub_rn(x, __fmul_rn(w, 0.5f));
            float ym = __fsub_rn(y, __fmul_rn(h, 0.5f));
            float xM = __fadd_rn(xm, w);
            float yM = __fadd_rn(ym, h);
            float c0 = fminf(fmaxf(__fmul_rn(xm, rw), 0.0f), W);
            float c1 = fminf(fmaxf(__fmul_rn(ym, rh), 0.0f), H);
            float c2 = fminf(fmaxf(__fmul_rn(xM, rw), 0.0f), W);
            float c3 = fminf(fmaxf(__fmul_rn(yM, rh), 0.0f), H);
            g_box[gi]   = make_float4(c0, c1, c2, c3);
            g_area[gi]  = __fmul_rn(fmaxf(__fsub_rn(c2, c0), 0.0f),
                                    fmaxf(__fsub_rn(c3, c1), 0.0f));
            g_score[gi] = sc;
            g_orig[gi]  = (int)o;
        } else {
            g_box[gi]   = make_float4(0.f, 0.f, 0.f, 0.f);
            g_area[gi]  = 0.f;
            g_score[gi] = -1.0f;
            g_orig[gi]  = 0;
        }
    }
    if (tid == 0) g_nvalid[b] = (M < TOPK) ? M : TOPK;
}

// ---------------------------------------------------------------------------
// K4: fused windowed NMS + emit (unchanged from the 191µs passing version).
// ---------------------------------------------------------------------------
#define SM_BOX    0                       // float4[2048]  32768
#define SM_AREA   32768                   // float [2048]   8192
#define SM_KBOX   40960                   // float4[300]    4800
#define SM_KAREA  45760                   // float [300]    1200
#define SM_KIDX   46960                   // int   [300]    1200
#define SM_MAT    48160                   // u32 [256*8]    8192
#define SM_SUP    56352                   // u32 [256]      1024
#define SM_KEPT   57376                   // int            4
#define SM_TOTAL  57408

__global__ __launch_bounds__(1024, 1)
void yolo_nms_emit(const float* __restrict__ preds,
                   float* __restrict__ out) {
    extern __shared__ unsigned char sm[];
    float4* sbox  = (float4*)(sm + SM_BOX);
    float*  sarea = (float*) (sm + SM_AREA);
    float4* kbox  = (float4*)(sm + SM_KBOX);
    float*  karea = (float*) (sm + SM_KAREA);
    int*    kidx  = (int*)   (sm + SM_KIDX);
    u32*    mat   = (u32*)   (sm + SM_MAT);
    u32*    ssup  = (u32*)   (sm + SM_SUP);
    int*    skept = (int*)   (sm + SM_KEPT);

    const int b = blockIdx.x, tid = threadIdx.x;
    const int nv = g_nvalid[b];

    for (int r = tid; r < TOPK; r += 1024) {
        sbox[r]  = g_box[b * TOPK + r];
        sarea[r] = g_area[b * TOPK + r];
    }
    if (tid == 0) *skept = 0;

    for (int wbase = 0; wbase < nv; wbase += WSZ) {
        __syncthreads();
        const int kept = *skept;
        if (kept >= MAXDET) break;
        const int wn = (nv - wbase < WSZ) ? (nv - wbase) : WSZ;
        if (tid < WSZ) ssup[tid] = 0;
        __syncthreads();

        // phase A: candidates vs kept pivots (4 threads / candidate)
        {
            const int c = tid >> 2, q = tid & 3;
            if (c < wn && kept > 0) {
                float4 a = sbox[wbase + c];
                float aa = sarea[wbase + c];
                bool hit = false;
                for (int p = q; p < kept; p += 4)
                    if (sup_test(kbox[p], karea[p], a, aa)) { hit = true; break; }
                if (hit) atomicOr(&ssup[c], 1u);
            }
        }
        // phase B: intra-window bitmatrix (4 threads / row, 2 words)
        {
            const int r = tid >> 2;
            if (r < wn) {
                float4 a = sbox[wbase + r];
                float aa = sarea[wbase + r];
                #pragma unroll
                for (int h = 0; h < 2; ++h) {
                    const int w  = (tid & 3) * 2 + h;
                    const int j0 = w * 32;
                    u32 bits = 0;
                    if (j0 + 31 > r) {
                        #pragma unroll 8
                        for (int k = 0; k < 32; ++k) {
                            int j = j0 + k;
                            if (j > r && j < wn &&
                                sup_test(a, aa, sbox[wbase + j], sarea[wbase + j]))
                                bits |= (1u << k);
                        }
                    }
                    mat[r * WW + w] = bits;
                }
            }
        }
        __syncthreads();

        // phase C: greedy scan (warp 0, alive masks in registers)
        if (tid < 32) {
            const int lane = tid;
            u32 alive = 0;
            #pragma unroll
            for (int w = 0; w < WW; ++w) {
                int c = w * 32 + lane;
                u32 wd = __ballot_sync(0xFFFFFFFFu, (c < wn) && (ssup[c] == 0));
                if (lane == w) alive = wd;
            }
            int k2 = kept;
            while (k2 < MAXDET) {
                u32 bal = __ballot_sync(0xFFFFFFFFu, alive != 0);
                if (!bal) break;
                int l = __ffs(bal) - 1;
                int bit = __ffs(alive) - 1;
                bit = __shfl_sync(0xFFFFFFFFu, bit, l);
                int c = l * 32 + bit;
                if (lane == 0) {
                    kidx[k2]  = wbase + c;
                    kbox[k2]  = sbox[wbase + c];
                    karea[k2] = sarea[wbase + c];
                }
                k2++;
                if (k2 >= MAXDET) break;
                u32 rw = (lane < WW) ? mat[c * WW + lane] : 0u;
                if (lane == l) alive &= ~(1u << bit);
                alive &= ~rw;
            }
            if (lane == 0) *skept = k2;
        }
    }
    __syncthreads();
    const int kept = *skept;

    for (int r = tid; r < MAXDET; r += 1024) {
        float o0 = 0.f, o1 = 0.f, o2 = 0.f, o3 = 0.f, o4 = 0.f, o5 = 0.f;
        if (r < kept) {
            int i = kidx[r];
            float4 bx = sbox[i];
            o0 = bx.x; o1 = bx.y; o2 = bx.z; o3 = bx.w;
            o4 = g_score[b * TOPK + i];
            const float* p = preds + ((size_t)b * NPRED + g_orig[b * TOPK + i]) * NCH + 5;
            float best = p[0]; int bi = 0;
            #pragma unroll 8
            for (int c = 1; c < 80; ++c) {
                float v = p[c];
                if (v > best) { best = v; bi = c; }
            }
            o5 = (float)(bi + 1);
        }
        float* po = out + ((size_t)b * MAXDET + r) * 6;
        po[0] = o0; po[1] = o1; po[2] = o2;
        po[3] = o3; po[4] = o4; po[5] = o5;
    }
}

// ---------------------------------------------------------------------------
extern "C" void kernel_launch(void* const* d_in, const int* in_sizes, int n_in,
                              void* d_out, int out_size) {
    const float* preds = (const float*)d_in[0];
    const int*   iszs  = (const int*)d_in[1];
    float*       out   = (float*)d_out;

    cudaFuncSetAttribute(k_sortdec,
                         cudaFuncAttributeMaxDynamicSharedMemorySize,
                         CANDCAP * (int)sizeof(u64));       // 64KB
    cudaFuncSetAttribute(yolo_nms_emit,
                         cudaFuncAttributeMaxDynamicSharedMemorySize, SM_TOTAL);

    k_hist<<<dim3(NBATCH, HBLK), 512>>>(preds);
    k_compact<<<NBATCH, 1024>>>(preds);
    k_sortdec<<<NBATCH, 1024, CANDCAP * sizeof(u64)>>>(preds, iszs);
    yolo_nms_emit<<<NBATCH, 1024, SM_TOTAL>>>(preds, out);
}

// round 17
// speedup vs baseline: 1.2346x; 1.2346x over previous
#include <cuda_runtime.h>
#include <cstdint>

typedef unsigned long long u64;
typedef unsigned int u32;

#define NPRED   25200
#define NCH     85
#define NBATCH  16
#define TOPK    2048
#define MAXDET  300
#define CONF    0.25f
#define NMS_T   0.45f
#define WSZ     256         // NMS window size
#define WW      8           // u32 words per window row (WSZ/32)
#define NWIN    (TOPK / WSZ)     // 8
#define NBIN    8192
#define HBLK    4           // histogram sub-blocks per batch
#define HCHUNK  (NPRED / HBLK)   // 6300
#define CANDCAP 8192
#define KBASE   0xBE800000u // sortable(+0.25); valid keys in (KBASE, KBASE+2^24)

__device__ u32    g_hist[NBATCH * HBLK * NBIN];
__device__ float4 g_box  [NBATCH * TOPK];
__device__ float  g_area [NBATCH * TOPK];
__device__ float  g_score[NBATCH * TOPK];
__device__ int    g_orig [NBATCH * TOPK];
__device__ int    g_nvalid[NBATCH];
__device__ u32    g_intra[NBATCH * NWIN * WSZ * WW];   // per-window bitmatrices, 1MB

__device__ __forceinline__ unsigned f2sortable(float f) {
    unsigned v = __float_as_uint(f);
    return (v & 0x80000000u) ? ~v : (v | 0x80000000u);
}
__device__ __forceinline__ float sortable2f(unsigned s) {
    unsigned v = (s & 0x80000000u) ? (s & 0x7FFFFFFFu) : ~s;
    return __uint_as_float(v);
}

// Bitwise-identical to (inter/(union+1e-7)) > 0.45: multiply-compare bracket,
// exact division only inside the ±4e-6 ambiguity band (div err ~6e-8).
__device__ __forceinline__ bool sup_test(float4 a, float aa, float4 bb, float ab) {
    float ltx = fmaxf(a.x, bb.x);
    float lty = fmaxf(a.y, bb.y);
    float rbx = fminf(a.z, bb.z);
    float rby = fminf(a.w, bb.w);
    float iw  = fmaxf(__fsub_rn(rbx, ltx), 0.0f);
    float ih  = fmaxf(__fsub_rn(rby, lty), 0.0f);
    float inter = __fmul_rn(iw, ih);
    float uni   = __fsub_rn(__fadd_rn(ab, aa), inter);
    float u     = __fadd_rn(uni, 1e-7f);
    if (inter > __fmul_rn(u, 0.45000180f)) return true;
    if (inter < __fmul_rn(u, 0.44999820f)) return false;
    return __fdiv_rn(inter, u) > NMS_T;
}

// ---------------------------------------------------------------------------
// K1: per (batch, sub-block) histogram of score keys.
// ---------------------------------------------------------------------------
__global__ __launch_bounds__(512, 2)
void k_hist(const float* __restrict__ preds) {
    __shared__ u32 h[NBIN];
    const int b = blockIdx.x, p = blockIdx.y, tid = threadIdx.x;
    for (int i = tid; i < NBIN; i += 512) h[i] = 0;
    __syncthreads();
    const int start = p * HCHUNK;
    for (int i = start + tid; i < start + HCHUNK; i += 512) {
        float sv = preds[((size_t)b * NPRED + i) * NCH + 4];
        if (sv > CONF) {
            u32 s = f2sortable(sv);
            u32 bin = (s - KBASE) >> 11;
            if (bin > NBIN - 1) bin = NBIN - 1;
            atomicAdd(&h[bin], 1u);
        }
    }
    __syncthreads();
    u32* dst = g_hist + ((size_t)(b * HBLK + p) << 13);
    for (int i = tid; i < NBIN; i += 512) dst[i] = h[i];
}

// ---------------------------------------------------------------------------
// K2 (FUSED k_compact + k_sortdec): per batch — threshold from histogram,
// compact keys >= threshold directly into smem, bitonic sort in place,
// decode top-2048. Deletes the g_cand gmem round-trip and one launch.
// Compaction order is nondeterministic (smem atomic) but keys are distinct
// (index in low bits) and the sort erases order -> deterministic output.
// ---------------------------------------------------------------------------
#define SEL_KEYS  0                    // u64 [8192]  65536
#define SEL_BIN   65536                // u32 [8192]  32768
#define SEL_PART  98304                // u32 [1024]   4096
#define SEL_MISC  102400               // int [2]: sB, cnt
#define SEL_TOTAL 102416

__global__ __launch_bounds__(1024, 1)
void k_select(const float* __restrict__ preds,
              const int* __restrict__ image_sizes) {
    extern __shared__ unsigned char smraw[];
    u64* keys   = (u64*)(smraw + SEL_KEYS);
    u32* binCnt = (u32*)(smraw + SEL_BIN);
    u32* part   = (u32*)(smraw + SEL_PART);
    int* misc   = (int*)(smraw + SEL_MISC);   // [0]=boundary bin, [1]=count
    const int b = blockIdx.x, tid = threadIdx.x;

    // reduce 4 sub-histograms, per-thread group sums
    const u32* hb = g_hist + ((size_t)(b * HBLK) << 13);
    u32 sum = 0;
    #pragma unroll
    for (int k = 0; k < 8; ++k) {
        int bin = tid * 8 + k;
        u32 c = hb[bin] + hb[NBIN + bin] + hb[2 * NBIN + bin] + hb[3 * NBIN + bin];
        binCnt[bin] = c;
        sum += c;
    }
    part[tid] = sum;
    __syncthreads();
    for (int d = 1; d < 1024; d <<= 1) {           // inclusive suffix scan
        u32 v = (tid + d < 1024) ? part[tid + d] : 0u;
        __syncthreads();
        part[tid] += v;
        __syncthreads();
    }
    if (tid == 0) { misc[0] = 0; misc[1] = 0; }
    __syncthreads();
    {
        u32 below = (tid + 1 < 1024) ? part[tid + 1] : 0u;
        if (part[tid] >= TOPK && below < TOPK) {   // unique boundary group
            u32 acc = below;
            int B = tid * 8;
            for (int k = 7; k >= 0; --k) {
                acc += binCnt[tid * 8 + k];
                if (acc >= TOPK) { B = tid * 8 + k; break; }
            }
            misc[0] = B;
        }
    }
    __syncthreads();
    const u32 thr = KBASE + ((u32)misc[0] << 11);

    // compact straight into smem
    for (int i = tid; i < NPRED; i += 1024) {
        float sv = preds[((size_t)b * NPRED + i) * NCH + 4];
        if (sv > CONF) {
            u32 s = f2sortable(sv);
            if (s >= thr) {
                int pos = atomicAdd(&misc[1], 1);
                if (pos < CANDCAP)
                    keys[pos] = ((u64)s << 32) | (u32)(~(u32)i);
            }
        }
    }
    __syncthreads();
    int M = misc[1]; if (M > CANDCAP) M = CANDCAP;
    int n = 2048;
    while (n < M) n <<= 1;                         // <= 8192 by CANDCAP
    for (int r = M + tid; r < n; r += 1024) keys[r] = 0ULL;   // pad

    // bitonic sort descending, in place
    for (u32 k = 2; k <= (u32)n; k <<= 1) {
        for (u32 j = k >> 1; j > 0; j >>= 1) {
            __syncthreads();
            for (u32 t = tid; t < (u32)n / 2; t += 1024) {
                u32 i = 2u * t - (t & (j - 1));
                u32 l = i + j;
                u64 a = keys[i], e = keys[l];
                bool dir = ((i & k) == 0);
                if ((a < e) == dir) { keys[i] = e; keys[l] = a; }
            }
        }
    }
    __syncthreads();

    // decode/clip top-2048 into SoA scratch
    const float H  = (float)image_sizes[b * 2 + 0];
    const float W  = (float)image_sizes[b * 2 + 1];
    const float rh = __fdiv_rn(H, 640.0f);
    const float rw = __fdiv_rn(W, 640.0f);

    for (int r = tid; r < TOPK; r += 1024) {
        u64 key = (r < n) ? keys[r] : 0ULL;
        unsigned o = ~((unsigned)key);
        int gi = b * TOPK + r;
        if (key != 0ULL && o < NPRED) {
            float sc = sortable2f((unsigned)(key >> 32));
            const float* p = preds + ((size_t)b * NPRED + o) * NCH;
            float x = p[0], y = p[1], w = p[2], h = p[3];
            float xm = __fsub_rn(x, __fmul_rn(w, 0.5f));
            float ym = __fsub_rn(y, __fmul_rn(h, 0.5f));
            float xM = __fadd_rn(xm, w);
            float yM = __fadd_rn(ym, h);
            float c0 = fminf(fmaxf(__fmul_rn(xm, rw), 0.0f), W);
            float c1 = fminf(fmaxf(__fmul_rn(ym, rh), 0.0f), H);
            float c2 = fminf(fmaxf(__fmul_rn(xM, rw), 0.0f), W);
            float c3 = fminf(fmaxf(__fmul_rn(yM, rh), 0.0f), H);
            g_box[gi]   = make_float4(c0, c1, c2, c3);
            g_area[gi]  = __fmul_rn(fmaxf(__fsub_rn(c2, c0), 0.0f),
                                    fmaxf(__fsub_rn(c3, c1), 0.0f));
            g_score[gi] = sc;
            g_orig[gi]  = (int)o;
        } else {
            g_box[gi]   = make_float4(0.f, 0.f, 0.f, 0.f);
            g_area[gi]  = 0.f;
            g_score[gi] = -1.0f;
            g_orig[gi]  = 0;
        }
    }
    if (tid == 0) g_nvalid[b] = (M < TOPK) ? M : TOPK;
}

// ---------------------------------------------------------------------------
// K3: intra-window 256x256 bitmatrices for ALL (batch, window) pairs in
// parallel — extracted from the serial NMS loop (the 133µs culprit: all of a
// batch's phase-B LDS traffic through one SM). 128 blocks -> 8x parallelism.
// ---------------------------------------------------------------------------
__global__ __launch_bounds__(1024, 1)
void k_intra() {
    __shared__ float4 sb[WSZ];
    __shared__ float  sa[WSZ];
    const int b = blockIdx.x, w = blockIdx.y, tid = threadIdx.x;
    const int base = w * WSZ;
    const int nv = g_nvalid[b];
    const int wn = (nv - base < WSZ) ? (nv - base) : WSZ;
    if (wn <= 0) return;                    // block-uniform; never read by K4

    if (tid < WSZ && tid < wn) {
        sb[tid] = g_box[b * TOPK + base + tid];
        sa[tid] = g_area[b * TOPK + base + tid];
    }
    __syncthreads();

    const int r = tid >> 2;
    if (r >= wn) return;                    // no barriers after this point
    const float4 a  = sb[r];
    const float  aa = sa[r];
    u32* dst = g_intra + (((size_t)(b * NWIN + w)) * WSZ + r) * WW;
    #pragma unroll
    for (int h = 0; h < 2; ++h) {
        const int wd = (tid & 3) * 2 + h;
        const int j0 = wd * 32;
        u32 bits = 0;
        if (j0 + 31 > r) {
            #pragma unroll 8
            for (int k = 0; k < 32; ++k) {
                int j = j0 + k;
                if (j > r && j < wn && sup_test(a, aa, sb[j], sa[j]))
                    bits |= (1u << k);
            }
        }
        dst[wd] = bits;
    }
}

// ---------------------------------------------------------------------------
// K4: serial NMS per batch: per window, stage precomputed matrix (L2->smem),
//     phase A (candidates vs kept pivots — the only serial-dependent tests),
//     warp-0 register-mask scan, then emit top-300.
// ---------------------------------------------------------------------------
#define SM_BOX    0                       // float4[2048]  32768
#define SM_AREA   32768                   // float [2048]   8192
#define SM_KBOX   40960                   // float4[300]    4800
#define SM_KAREA  45760                   // float [300]    1200
#define SM_KIDX   46960                   // int   [300]    1200
#define SM_MAT    48160                   // u32 [256*8]    8192
#define SM_SUP    56352                   // u32 [256]      1024
#define SM_KEPT   57376                   // int            4
#define SM_TOTAL  57408

__global__ __launch_bounds__(1024, 1)
void yolo_nms_emit(const float* __restrict__ preds,
                   float* __restrict__ out) {
    extern __shared__ unsigned char sm[];
    float4* sbox  = (float4*)(sm + SM_BOX);
    float*  sarea = (float*) (sm + SM_AREA);
    float4* kbox  = (float4*)(sm + SM_KBOX);
    float*  karea = (float*) (sm + SM_KAREA);
    int*    kidx  = (int*)   (sm + SM_KIDX);
    u32*    mat   = (u32*)   (sm + SM_MAT);
    u32*    ssup  = (u32*)   (sm + SM_SUP);
    int*    skept = (int*)   (sm + SM_KEPT);

    const int b = blockIdx.x, tid = threadIdx.x;
    const int nv = g_nvalid[b];

    for (int r = tid; r < TOPK; r += 1024) {
        sbox[r]  = g_box[b * TOPK + r];
        sarea[r] = g_area[b * TOPK + r];
    }
    if (tid == 0) *skept = 0;

    for (int wbase = 0; wbase < nv; wbase += WSZ) {
        __syncthreads();
        const int kept = *skept;
        if (kept >= MAXDET) break;
        const int wn = (nv - wbase < WSZ) ? (nv - wbase) : WSZ;
        if (tid < WSZ) ssup[tid] = 0;

        // stage this window's precomputed intra matrix: 2048 u32 (8KB).
        // LDG issued before phase A so latency overlaps the test loop.
        {
            const u32* src = g_intra +
                ((size_t)(b * NWIN + (wbase >> 8))) * WSZ * WW;
            mat[tid]        = src[tid];
            mat[tid + 1024] = src[tid + 1024];
        }
        __syncthreads();

        // phase A: candidates vs kept pivots (4 threads / candidate)
        {
            const int c = tid >> 2, q = tid & 3;
            if (c < wn && kept > 0) {
                float4 a = sbox[wbase + c];
                float aa = sarea[wbase + c];
                bool hit = false;
                for (int p = q; p < kept; p += 4)
                    if (sup_test(kbox[p], karea[p], a, aa)) { hit = true; break; }
                if (hit) atomicOr(&ssup[c], 1u);
            }
        }
        __syncthreads();

        // phase C: greedy scan (warp 0, alive masks in registers)
        if (tid < 32) {
            const int lane = tid;
            u32 alive = 0;
            #pragma unroll
            for (int w = 0; w < WW; ++w) {
                int c = w * 32 + lane;
                u32 wd = __ballot_sync(0xFFFFFFFFu, (c < wn) && (ssup[c] == 0));
                if (lane == w) alive = wd;
            }
            int k2 = kept;
            while (k2 < MAXDET) {
                u32 bal = __ballot_sync(0xFFFFFFFFu, alive != 0);
                if (!bal) break;
                int l = __ffs(bal) - 1;
                int bit = __ffs(alive) - 1;
                bit = __shfl_sync(0xFFFFFFFFu, bit, l);
                int c = l * 32 + bit;
                if (lane == 0) {
                    kidx[k2]  = wbase + c;
                    kbox[k2]  = sbox[wbase + c];
                    karea[k2] = sarea[wbase + c];
                }
                k2++;
                if (k2 >= MAXDET) break;
                u32 rw = (lane < WW) ? mat[c * WW + lane] : 0u;
                if (lane == l) alive &= ~(1u << bit);
                alive &= ~rw;
            }
            if (lane == 0) *skept = k2;
        }
    }
    __syncthreads();
    const int kept = *skept;

    for (int r = tid; r < MAXDET; r += 1024) {
        float o0 = 0.f, o1 = 0.f, o2 = 0.f, o3 = 0.f, o4 = 0.f, o5 = 0.f;
        if (r < kept) {
            int i = kidx[r];
            float4 bx = sbox[i];
            o0 = bx.x; o1 = bx.y; o2 = bx.z; o3 = bx.w;
            o4 = g_score[b * TOPK + i];
            const float* p = preds + ((size_t)b * NPRED + g_orig[b * TOPK + i]) * NCH + 5;
            float best = p[0]; int bi = 0;
            #pragma unroll 8
            for (int c = 1; c < 80; ++c) {
                float v = p[c];
                if (v > best) { best = v; bi = c; }
            }
            o5 = (float)(bi + 1);
        }
        float* po = out + ((size_t)b * MAXDET + r) * 6;
        po[0] = o0; po[1] = o1; po[2] = o2;
        po[3] = o3; po[4] = o4; po[5] = o5;
    }
}

// ---------------------------------------------------------------------------
extern "C" void kernel_launch(void* const* d_in, const int* in_sizes, int n_in,
                              void* d_out, int out_size) {
    const float* preds = (const float*)d_in[0];
    const int*   iszs  = (const int*)d_in[1];
    float*       out   = (float*)d_out;

    cudaFuncSetAttribute(k_select,
                         cudaFuncAttributeMaxDynamicSharedMemorySize, SEL_TOTAL);
    cudaFuncSetAttribute(yolo_nms_emit,
                         cudaFuncAttributeMaxDynamicSharedMemorySize, SM_TOTAL);

    k_hist<<<dim3(NBATCH, HBLK), 512>>>(preds);
    k_select<<<NBATCH, 1024, SEL_TOTAL>>>(preds, iszs);
    k_intra<<<dim3(NBATCH, NWIN), 1024>>>();
    yolo_nms_emit<<<NBATCH, 1024, SM_TOTAL>>>(preds, out);
}